// round 1
// baseline (speedup 1.0000x reference)
#include <cuda_runtime.h>
#include <math.h>

// ---------------------------------------------------------------------------
// GCN encoder stack:
//   z   = relu(A1n(relu(A1n(x W1)+b1) W2)+b2)
//   z_g = relu(A2n(relu((A2n z) W3 + b3) W4)+b4)   (layer3 reordered: A(zW)= (Az)W)
// A*n = D^-1/2 (A+I) D^-1/2 applied edge-wise + self-loop term.
// ---------------------------------------------------------------------------

#define NMAX 50048

__device__ float g_b512a[(size_t)NMAX * 512];
__device__ float g_b512b[(size_t)NMAX * 512];
__device__ float g_b256a[(size_t)NMAX * 256];
__device__ float g_b256b[(size_t)NMAX * 256];
__device__ int   g_deg1[NMAX];
__device__ int   g_deg2[NMAX];
__device__ float g_inv1[NMAX];
__device__ float g_inv2[NMAX];

// ---------------------------------------------------------------------------
// helpers
// ---------------------------------------------------------------------------
__device__ __forceinline__ void red_add_v4(float* addr, float4 v) {
    // sm_90+ vectorized fp32 global reduction (PTX ISA 8.1+)
    asm volatile("red.global.add.v4.f32 [%0], {%1, %2, %3, %4};"
                 :: "l"(addr), "f"(v.x), "f"(v.y), "f"(v.z), "f"(v.w)
                 : "memory");
}

// ---------------------------------------------------------------------------
// degree / normalization
// ---------------------------------------------------------------------------
__global__ void k_zero_deg(int* d1, int* d2, int n) {
    int i = blockIdx.x * blockDim.x + threadIdx.x;
    if (i < n) { d1[i] = 0; d2[i] = 0; }
}

__global__ void k_deg(const int* __restrict__ dst, int E, int* deg) {
    int i = blockIdx.x * blockDim.x + threadIdx.x;
    if (i < E) atomicAdd(&deg[dst[i]], 1);
}

__global__ void k_inv(const int* __restrict__ d1, const int* __restrict__ d2,
                      float* i1, float* i2, int n) {
    int i = blockIdx.x * blockDim.x + threadIdx.x;
    if (i < n) {
        i1[i] = rsqrtf((float)d1[i] + 1.0f);
        i2[i] = rsqrtf((float)d2[i] + 1.0f);
    }
}

// ---------------------------------------------------------------------------
// agg init: agg[i,:] = h[i,:] * inv[i]^2 (+ bias)   (self-loop + bias term)
// ---------------------------------------------------------------------------
template<int D>
__global__ void k_init_agg(const float* __restrict__ h, const float* __restrict__ inv,
                           const float* __restrict__ bias, float* __restrict__ agg, int n) {
    constexpr int C4 = D / 4;
    int idx = blockIdx.x * blockDim.x + threadIdx.x;
    if (idx >= n * C4) return;
    int row = idx / C4;
    int col = idx - row * C4;
    float s = inv[row]; s *= s;
    float4 v = ((const float4*)h)[idx];
    float4 o;
    if (bias) {
        float4 b = ((const float4*)bias)[col];
        o = make_float4(v.x * s + b.x, v.y * s + b.y, v.z * s + b.z, v.w * s + b.w);
    } else {
        o = make_float4(v.x * s, v.y * s, v.z * s, v.w * s);
    }
    ((float4*)agg)[idx] = o;
}

// ---------------------------------------------------------------------------
// edge scatter: agg[dst,:] += h[src,:] * inv[src]*inv[dst]
// ---------------------------------------------------------------------------
template<int D>
__global__ __launch_bounds__(256)
void k_scatter(const int* __restrict__ src, const int* __restrict__ dst,
               const float* __restrict__ inv, const float* __restrict__ h,
               float* agg, int E) {
    constexpr int TPE  = D / 4;       // threads per edge (float4 lanes)
    constexpr int EPB  = 256 / TPE;   // edges in flight per block
    constexpr int ITER = 8;
    int lane = threadIdx.x & (TPE - 1);
    int sub  = threadIdx.x / TPE;
    int base = blockIdx.x * (EPB * ITER) + sub;
#pragma unroll
    for (int it = 0; it < ITER; it++) {
        int e = base + it * EPB;
        if (e < E) {
            int s = src[e], d = dst[e];
            float c = inv[s] * inv[d];
            float4 v = *(const float4*)(h + (size_t)s * D + lane * 4);
            red_add_v4(agg + (size_t)d * D + lane * 4,
                       make_float4(v.x * c, v.y * c, v.z * c, v.w * c));
        }
    }
}

// ---------------------------------------------------------------------------
// relu copy (in==out allowed)
// ---------------------------------------------------------------------------
__global__ void k_relu(const float* __restrict__ in, float* __restrict__ out, int n4) {
    int i = blockIdx.x * blockDim.x + threadIdx.x;
    if (i >= n4) return;
    float4 v = ((const float4*)in)[i];
    v.x = fmaxf(v.x, 0.f); v.y = fmaxf(v.y, 0.f);
    v.z = fmaxf(v.z, 0.f); v.w = fmaxf(v.w, 0.f);
    ((float4*)out)[i] = v;
}

// ---------------------------------------------------------------------------
// SGEMM: C[M,N] = A[M,K] * B[K,N] (+bias, +relu). 128x128x8 tiles, 256 thr,
// 8x8 per thread. N,K multiples of 128/8; M guarded.
// ---------------------------------------------------------------------------
template<bool HAS_BIAS, bool RELU>
__global__ __launch_bounds__(256)
void k_sgemm(const float* __restrict__ A, const float* __restrict__ B,
             const float* __restrict__ bias, float* __restrict__ C,
             int M, int N, int K) {
    __shared__ float As[8][128];
    __shared__ float Bs[8][128];
    const int tid = threadIdx.x;
    const int bx = blockIdx.x * 128;        // col tile
    const int by = blockIdx.y * 128;        // row tile
    const int tx = (tid % 16) * 8;
    const int ty = (tid / 16) * 8;
    const int arow = tid >> 1;
    const int acol = (tid & 1) * 4;
    const int brow = tid >> 5;
    const int bcol = (tid & 31) * 4;

    float acc[8][8];
#pragma unroll
    for (int i = 0; i < 8; i++)
#pragma unroll
        for (int j = 0; j < 8; j++) acc[i][j] = 0.f;

    const bool arow_ok = (by + arow) < M;
    const float* Aptr = A + (size_t)(by + arow) * K + acol;
    const float* Bptr = B + (size_t)brow * N + bx + bcol;

    for (int k0 = 0; k0 < K; k0 += 8) {
        float4 av = make_float4(0.f, 0.f, 0.f, 0.f);
        if (arow_ok) av = *(const float4*)(Aptr + k0);
        float4 bv = *(const float4*)(Bptr + (size_t)k0 * N);
        As[acol + 0][arow] = av.x;
        As[acol + 1][arow] = av.y;
        As[acol + 2][arow] = av.z;
        As[acol + 3][arow] = av.w;
        *(float4*)&Bs[brow][bcol] = bv;
        __syncthreads();
#pragma unroll
        for (int kk = 0; kk < 8; kk++) {
            float ar[8], br[8];
            *(float4*)&ar[0] = *(const float4*)&As[kk][ty];
            *(float4*)&ar[4] = *(const float4*)&As[kk][ty + 4];
            *(float4*)&br[0] = *(const float4*)&Bs[kk][tx];
            *(float4*)&br[4] = *(const float4*)&Bs[kk][tx + 4];
#pragma unroll
            for (int i = 0; i < 8; i++)
#pragma unroll
                for (int j = 0; j < 8; j++)
                    acc[i][j] = fmaf(ar[i], br[j], acc[i][j]);
        }
        __syncthreads();
    }

    float bvals[8];
    if (HAS_BIAS) {
        *(float4*)&bvals[0] = *(const float4*)(bias + bx + tx);
        *(float4*)&bvals[4] = *(const float4*)(bias + bx + tx + 4);
    }
#pragma unroll
    for (int i = 0; i < 8; i++) {
        int r = by + ty + i;
        if (r < M) {
            float o[8];
#pragma unroll
            for (int j = 0; j < 8; j++) {
                float v = acc[i][j];
                if (HAS_BIAS) v += bvals[j];
                if (RELU) v = fmaxf(v, 0.f);
                o[j] = v;
            }
            *(float4*)(C + (size_t)r * N + bx + tx)     = *(float4*)&o[0];
            *(float4*)(C + (size_t)r * N + bx + tx + 4) = *(float4*)&o[4];
        }
    }
}

// ---------------------------------------------------------------------------
// launch
// ---------------------------------------------------------------------------
static inline int cdiv(int a, int b) { return (a + b - 1) / b; }

extern "C" void kernel_launch(void* const* d_in, const int* in_sizes, int n_in,
                              void* d_out, int out_size) {
    if (n_in < 11) return;
    const float* x  = (const float*)d_in[0];
    const int* ei1  = (const int*)d_in[1];
    const int* ei2  = (const int*)d_in[2];
    const float* W1 = (const float*)d_in[3];
    const float* b1 = (const float*)d_in[4];
    const float* W2 = (const float*)d_in[5];
    const float* b2 = (const float*)d_in[6];
    const float* W3 = (const float*)d_in[7];
    const float* b3 = (const float*)d_in[8];
    const float* W4 = (const float*)d_in[9];
    const float* b4 = (const float*)d_in[10];

    const int N  = in_sizes[0] / 512;
    const int E1 = in_sizes[1] / 2;
    const int E2 = in_sizes[2] / 2;
    const int* src1 = ei1;
    const int* dst1 = ei1 + E1;
    const int* src2 = ei2;
    const int* dst2 = ei2 + E2;

    float *b512a, *b512b, *b256a, *b256b, *inv1, *inv2;
    int *deg1, *deg2;
    cudaGetSymbolAddress((void**)&b512a, g_b512a);
    cudaGetSymbolAddress((void**)&b512b, g_b512b);
    cudaGetSymbolAddress((void**)&b256a, g_b256a);
    cudaGetSymbolAddress((void**)&b256b, g_b256b);
    cudaGetSymbolAddress((void**)&deg1,  g_deg1);
    cudaGetSymbolAddress((void**)&deg2,  g_deg2);
    cudaGetSymbolAddress((void**)&inv1,  g_inv1);
    cudaGetSymbolAddress((void**)&inv2,  g_inv2);

    float* out_z  = (float*)d_out;
    float* out_zg = out_z + (size_t)N * 256;

    const int rowTiles = cdiv(N, 128);

    // ---- degrees & normalization (re-zeroed each call) ----
    k_zero_deg<<<cdiv(N, 256), 256>>>(deg1, deg2, N);
    k_deg<<<cdiv(E1, 256), 256>>>(dst1, E1, deg1);
    k_deg<<<cdiv(E2, 256), 256>>>(dst2, E2, deg2);
    k_inv<<<cdiv(N, 256), 256>>>(deg1, deg2, inv1, inv2, N);

    // ---- Layer 1: h = x@W1 ; agg = A1n h + b1 ; relu (in place) ----
    k_sgemm<false, false><<<dim3(4, rowTiles), 256>>>(x, W1, nullptr, b512a, N, 512, 512);
    k_init_agg<512><<<cdiv(N * 128, 256), 256>>>(b512a, inv1, b1, b512b, N);
    k_scatter<512><<<cdiv(E1, 16), 256>>>(src1, dst1, inv1, b512a, b512b, E1);
    k_relu<<<cdiv(N * 128, 256), 256>>>(b512b, b512b, N * 128);

    // ---- Layer 2: h = z1@W2 ; agg = A1n h + b2 ; relu -> z (d_out) ----
    k_sgemm<false, false><<<dim3(2, rowTiles), 256>>>(b512b, W2, nullptr, b256a, N, 256, 512);
    k_init_agg<256><<<cdiv(N * 64, 256), 256>>>(b256a, inv1, b2, b256b, N);
    k_scatter<256><<<cdiv(E1, 32), 256>>>(src1, dst1, inv1, b256a, b256b, E1);
    k_relu<<<cdiv(N * 64, 256), 256>>>(b256b, out_z, N * 64);

    // ---- Layer 3 (aggregate-first): a = A2n z ; z3 = relu(a@W3 + b3) ----
    k_init_agg<256><<<cdiv(N * 64, 256), 256>>>(out_z, inv2, nullptr, b256a, N);
    k_scatter<256><<<cdiv(E2, 32), 256>>>(src2, dst2, inv2, out_z, b256a, E2);
    k_sgemm<true, true><<<dim3(4, rowTiles), 256>>>(b256a, W3, b3, b512a, N, 512, 256);

    // ---- Layer 4: h = z3@W4 ; agg = A2n h + b4 ; relu -> z_g ----
    k_sgemm<false, false><<<dim3(2, rowTiles), 256>>>(b512a, W4, nullptr, b256b, N, 256, 512);
    k_init_agg<256><<<cdiv(N * 64, 256), 256>>>(b256b, inv2, b4, b256a, N);
    k_scatter<256><<<cdiv(E2, 32), 256>>>(src2, dst2, inv2, b256b, b256a, E2);
    k_relu<<<cdiv(N * 64, 256), 256>>>(b256a, out_zg, N * 64);
}